// round 6
// baseline (speedup 1.0000x reference)
#include <cuda_runtime.h>

// C3 sparse-connectivity conv, 5x5 VALID, fp32, f32x2-packed FMA.
// x: [32,6,512,512] f32, weight: [16,6,5,5] f32, bias: [16] f32
// out: [32,16,508,508] f32
//
// Block: 256(w) x 4(h) output tile, one batch image. 256 threads = 8 warps.
// Warp = (row 0..3, oc-group 0..1): 1 output row x 8 output channels x 256 px.
// Each thread: TWO 4-px quads at x = 4*lane and 4*lane+128 (16B lane stride
// keeps LDS.128 conflict-free) -> each weight LDS feeds 20 FFMA2.
// Accumulators packed {p0,p1},{p2,p3} per quad -> fma.rn.f32x2.
// Weights pre-splatted {w,w} in smem so FFMA2 b-operand comes straight from LDS.

#define OW 508
#define OH 508
#define IW 512
#define IH 512
#define TILE_W 256
#define TILE_H 4
#define IN_W 260   // TILE_W + 4
#define IN_H 8     // TILE_H + 4

// ---- edge tables: 60 (ic,oc) edges, group0 = edges 0..30, group1 = 31..59 ----
__constant__ signed char E_IC[60] = {
    0,0,0,0, 1,1,1,1,1, 2,2,2,2,2,2,2, 3,3,3,3,3,3,3, 4,4,4,4,4, 5,5,5,
    0,0,0,0,0,0, 1,1,1,1,1, 2,2,2, 3,3,3, 4,4,4,4,4, 5,5,5,5,5,5,5};
__constant__ signed char E_OC[60] = {
    0,6,9,15, 0,1,6,7,15, 0,1,2,6,7,8,15, 1,2,6,7,8,9,15, 2,7,8,9,15, 8,9,15,
    4,5,10,11,12,14, 5,10,11,12,13, 11,13,14, 3,12,14, 3,4,10,12,13,
    3,4,5,10,11,13,14};

__device__ __forceinline__ unsigned long long pack2(float lo, float hi) {
    unsigned long long r;
    asm("mov.b64 %0, {%1, %2};" : "=l"(r) : "f"(lo), "f"(hi));
    return r;
}
__device__ __forceinline__ void unpack2(unsigned long long v, float& lo, float& hi) {
    asm("mov.b64 {%0, %1}, %2;" : "=f"(lo), "=f"(hi) : "l"(v));
}
__device__ __forceinline__ void ffma2(unsigned long long& d,
                                      unsigned long long a,
                                      unsigned long long b) {
    asm("fma.rn.f32x2 %0, %1, %2, %0;" : "+l"(d) : "l"(a), "l"(b));
}

#define WPG 930           // 31 edges * 30 (5 ky * 6 padded kx) float2 pairs
#define S_IN_FLOATS (6 * IN_H * IN_W)   // 12480

template <int GRP>
__device__ __forceinline__ void conv_group(
    const float* __restrict__ s_in,       // [6][IN_H][IN_W]
    const float2* __restrict__ s_wg,      // this group's weight pairs
    const float* __restrict__ s_b,
    float* __restrict__ out,
    int b, int x0, int oy, int row, int lane)
{
    constexpr int OFF[2][6]  = {{0, 4, 9, 16, 23, 28}, {0, 6, 11, 14, 17, 22}};
    constexpr int CNT[2][6]  = {{4, 5, 7, 7, 5, 3},    {6, 5, 3, 3, 5, 7}};
    constexpr int SLOT[2][31] = {
        {0,3,6,7, 0,1,3,4,7, 0,1,2,3,4,5,7, 1,2,3,4,5,6,7, 2,4,5,6,7, 5,6,7},
        {1,2,3,4,5,7, 2,3,4,5,6, 4,6,7, 0,5,7, 0,1,3,5,6, 0,1,2,3,4,6,7, 0,0}};
    constexpr int OCS[2][8]  = {{0, 1, 2, 6, 7, 8, 9, 15},
                                {3, 4, 5, 10, 11, 12, 13, 14}};

    const int lx = lane * 4;   // quad0 at lx, quad1 at lx+128

    // acc[s][0..1] = quad0 pairs {p0,p1},{p2,p3}; acc[s][2..3] = quad1 pairs
    unsigned long long acc[8][4];
#pragma unroll
    for (int s = 0; s < 8; ++s) {
        float bv = s_b[OCS[GRP][s]];
        unsigned long long bb = pack2(bv, bv);
        acc[s][0] = bb; acc[s][1] = bb; acc[s][2] = bb; acc[s][3] = bb;
    }

#pragma unroll
    for (int ic = 0; ic < 6; ++ic) {
#pragma unroll 1
        for (int ky = 0; ky < 5; ++ky) {
            const float* rp = &s_in[(ic * IN_H + row + ky) * IN_W + lx];
            // quad0 window v0[0..7], quad1 window v1[0..7]
            float4 a0 = *reinterpret_cast<const float4*>(rp);
            float4 a1 = *reinterpret_cast<const float4*>(rp + 4);
            float4 b0 = *reinterpret_cast<const float4*>(rp + 128);
            float4 b1 = *reinterpret_cast<const float4*>(rp + 132);
            float v0[8] = {a0.x, a0.y, a0.z, a0.w, a1.x, a1.y, a1.z, a1.w};
            float v1[8] = {b0.x, b0.y, b0.z, b0.w, b1.x, b1.y, b1.z, b1.w};
            unsigned long long P0[7], P1[7];
#pragma unroll
            for (int k = 0; k < 7; ++k) {
                P0[k] = pack2(v0[k], v0[k + 1]);
                P1[k] = pack2(v1[k], v1[k + 1]);
            }

#pragma unroll
            for (int jj = 0; jj < CNT[GRP][ic]; ++jj) {
                const int e = OFF[GRP][ic] + jj;
                const int s = SLOT[GRP][e];
                const float2* wp = &s_wg[e * 30 + ky * 6];
                ulonglong2 w01 = *reinterpret_cast<const ulonglong2*>(wp);
                ulonglong2 w23 = *reinterpret_cast<const ulonglong2*>(wp + 2);
                unsigned long long w4 =
                    *reinterpret_cast<const unsigned long long*>(wp + 4);
                // kx = 0..4, each weight pair feeds 4 FFMA2 (2 per quad)
                ffma2(acc[s][0], P0[0], w01.x);
                ffma2(acc[s][1], P0[2], w01.x);
                ffma2(acc[s][2], P1[0], w01.x);
                ffma2(acc[s][3], P1[2], w01.x);
                ffma2(acc[s][0], P0[1], w01.y);
                ffma2(acc[s][1], P0[3], w01.y);
                ffma2(acc[s][2], P1[1], w01.y);
                ffma2(acc[s][3], P1[3], w01.y);
                ffma2(acc[s][0], P0[2], w23.x);
                ffma2(acc[s][1], P0[4], w23.x);
                ffma2(acc[s][2], P1[2], w23.x);
                ffma2(acc[s][3], P1[4], w23.x);
                ffma2(acc[s][0], P0[3], w23.y);
                ffma2(acc[s][1], P0[5], w23.y);
                ffma2(acc[s][2], P1[3], w23.y);
                ffma2(acc[s][3], P1[5], w23.y);
                ffma2(acc[s][0], P0[4], w4);
                ffma2(acc[s][1], P0[6], w4);
                ffma2(acc[s][2], P1[4], w4);
                ffma2(acc[s][3], P1[6], w4);
            }
        }
    }

    const int ox0 = x0 + lx;
    const int ox1 = x0 + lx + 128;
#pragma unroll
    for (int s = 0; s < 8; ++s) {
        float* op = out + (((size_t)b * 16 + OCS[GRP][s]) * OH + oy) * OW;
        if (ox0 < OW) {
            float4 r;
            unpack2(acc[s][0], r.x, r.y);
            unpack2(acc[s][1], r.z, r.w);
            *reinterpret_cast<float4*>(op + ox0) = r;
        }
        if (ox1 < OW) {
            float4 r;
            unpack2(acc[s][2], r.x, r.y);
            unpack2(acc[s][3], r.z, r.w);
            *reinterpret_cast<float4*>(op + ox1) = r;
        }
    }
}

__global__ void __launch_bounds__(256, 2)
c3_kernel(const float* __restrict__ x,
          const float* __restrict__ wgt,
          const float* __restrict__ bias,
          float* __restrict__ out)
{
    extern __shared__ float smem[];
    float*  s_in = smem;                          // 12480 f = 49920 B
    float2* s_w2 = (float2*)(smem + S_IN_FLOATS); // 1860 f2 = 14880 B
    float*  s_b  = smem + S_IN_FLOATS + 2 * 2 * WPG;

    const int tid = threadIdx.x;
    const int x0 = blockIdx.x * TILE_W;
    const int y0 = blockIdx.y * TILE_H;
    const int b  = blockIdx.z;

    // ---- input tile (x OOB -> 0; y never OOB: y0+7 <= 511) ----
    const float* xb = x + (size_t)b * 6 * IH * IW;
    for (int i = tid; i < 6 * IN_H * IN_W; i += 256) {
        int c   = i / (IN_H * IN_W);
        int rem = i % (IN_H * IN_W);
        int r   = rem / IN_W;
        int col = rem % IN_W;
        int gx = x0 + col;
        float v = 0.0f;
        if (gx < IW) v = __ldg(&xb[(c * IH + y0 + r) * IW + gx]);
        s_in[(c * IN_H + r) * IN_W + col] = v;
    }
    // ---- weights, pre-splatted {w,w}: 60 edges x 25 taps ----
    for (int i = tid; i < 1500; i += 256) {
        int e  = i / 25;
        int k  = i % 25;
        int ky = k / 5, kx = k % 5;
        int ic = E_IC[e], oc = E_OC[e];
        int g  = (e >= 31);
        int eg = e - (g ? 31 : 0);
        float w = __ldg(&wgt[((oc * 6 + ic) * 5 + ky) * 5 + kx]);
        s_w2[g * WPG + eg * 30 + ky * 6 + kx] = make_float2(w, w);
    }
    if (tid < 16) s_b[tid] = __ldg(&bias[tid]);
    __syncthreads();

    const int wid  = tid >> 5;
    const int lane = tid & 31;
    const int row  = wid & 3;        // output row within tile
    const int grp  = wid >> 2;       // oc-group
    const int oy   = y0 + row;       // < 508 always (126*4+3)

    if (grp == 0)
        conv_group<0>(s_in, s_w2,       s_b, out, b, x0, oy, row, lane);
    else
        conv_group<1>(s_in, s_w2 + WPG, s_b, out, b, x0, oy, row, lane);
}

#define SMEM_BYTES ((S_IN_FLOATS + 2 * 2 * WPG + 16) * 4)   // 64864 B

extern "C" void kernel_launch(void* const* d_in, const int* in_sizes, int n_in,
                              void* d_out, int out_size)
{
    const float* x    = (const float*)d_in[0];  // [32,6,512,512]
    const float* wgt  = (const float*)d_in[1];  // [16,6,5,5]
    const float* bias = (const float*)d_in[2];  // [16]
    float* out = (float*)d_out;                 // [32,16,508,508]

    cudaFuncSetAttribute(c3_kernel,
                         cudaFuncAttributeMaxDynamicSharedMemorySize,
                         SMEM_BYTES);

    dim3 grid((OW + TILE_W - 1) / TILE_W,       // 2
              OH / TILE_H,                      // 127
              32);                              // batch
    c3_kernel<<<grid, 256, SMEM_BYTES>>>(x, wgt, bias, out);
}

// round 8
// speedup vs baseline: 2.8881x; 2.8881x over previous
#include <cuda_runtime.h>
#include <cuda_fp16.h>

// C3 sparse-connectivity conv via per-tap fp16 mma.sync (HMMA, f32 accum).
// x: [32,6,512,512] f32, weight: [16,6,5,5] f32, bias: [16] f32
// out: [32,16,508,508] f32
//
// For each output row r and tap (ky,kx):
//   D[128 px, 16 oc] += A[128, 8] * B_tap[16, 8]^T   (K = 6 ic + 2 zero pad)
// A = shifted view into a channels-last fp16 patch (16 B / pixel), so each
// mma fragment element is a single conflict-free LDS.32.
// CTA = 128 px (x) * 8 output rows (y) * 16 oc, one batch image.
// Warp = one output row: 8 M-tiles of 16 px, 2 oc-halves of 8.

#define OW 508
#define OH 508
#define IW 512
#define IH 512
#define TW 128
#define TH 8
#define PW 132            // TW + 4
#define PH 12             // TH + 4
#define PLANE (IH * IW)   // 262144

// smem byte offsets
#define SA 0                         // patch: [PH][PW] x 16B  = 25344 B
#define SB (PH * PW * 16)            // B: [25 tap][2 half][8 n][4 t] x 4B = 6400 B
#define SBIAS (SB + 6400)            // 16 floats
#define SMEM_TOTAL (SBIAS + 64)

// connectivity bitmask over ic for each oc (LeNet C3 table)
__constant__ unsigned CONN[16] = {
    0x07, 0x0E, 0x1C, 0x38, 0x31, 0x23, 0x0F, 0x1E,
    0x3C, 0x39, 0x33, 0x27, 0x1B, 0x36, 0x2D, 0x3F};

__device__ __forceinline__ unsigned pack_h2(float a, float b) {
    __half2 h = __floats2half2_rn(a, b);
    return *reinterpret_cast<unsigned*>(&h);
}

__global__ void __launch_bounds__(256, 2)
c3_hmma(const float* __restrict__ x,
        const float* __restrict__ wgt,
        const float* __restrict__ bias,
        float* __restrict__ out)
{
    __shared__ __align__(16) char smem[SMEM_TOTAL];

    const int tid = threadIdx.x;
    const int x0 = blockIdx.x * TW;
    const int y0 = blockIdx.y * TH;
    const int b  = blockIdx.z;

    // ---- build channels-last fp16 patch: [row][px][ic0..5, 0, 0] ----
    const float* xb = x + (size_t)b * 6 * PLANE;
    for (int i = tid; i < PH * PW; i += 256) {
        int row = i / PW, col = i % PW;
        int gy = y0 + row, gx = x0 + col;
        uint4 v = make_uint4(0u, 0u, 0u, 0u);
        if (gy < IH && gx < IW) {
            const float* p = xb + (size_t)gy * IW + gx;
            v.x = pack_h2(p[0],         p[PLANE]);
            v.y = pack_h2(p[2 * PLANE], p[3 * PLANE]);
            v.z = pack_h2(p[4 * PLANE], p[5 * PLANE]);
        }
        *reinterpret_cast<uint4*>(smem + SA + i * 16) = v;
    }
    // ---- B tiles: [tap][half][n(8)][t(4)] fp16-pairs (ic 2t, 2t+1), masked ----
    for (int i = tid; i < 1600; i += 256) {
        int t    = i & 3;
        int n    = (i >> 2) & 7;
        int half = (i >> 5) & 1;
        int tap  = i >> 6;
        int ky = tap / 5, kx = tap % 5;
        int oc = half * 8 + n;
        unsigned m = CONN[oc];
        float wa = 0.f, wb = 0.f;
        if (t < 3) {
            int ia = 2 * t, ib = 2 * t + 1;
            if (m & (1u << ia)) wa = wgt[((oc * 6 + ia) * 5 + ky) * 5 + kx];
            if (m & (1u << ib)) wb = wgt[((oc * 6 + ib) * 5 + ky) * 5 + kx];
        }
        *reinterpret_cast<unsigned*>(smem + SB + i * 4) = pack_h2(wa, wb);
    }
    if (tid < 16)
        reinterpret_cast<float*>(smem + SBIAS)[tid] = bias[tid];
    __syncthreads();

    const int wid  = tid >> 5;
    const int lane = tid & 31;
    const int g = lane >> 2;     // 0..7 : M row group / N col
    const int t = lane & 3;      // 0..3 : K pair index
    const int r = wid;           // output row within tile

    // acc[m-tile][oc-half][c0..c3], init with bias
    float acc[8][2][4];
    {
        const float* bs = reinterpret_cast<const float*>(smem + SBIAS);
#pragma unroll
        for (int h = 0; h < 2; ++h) {
            float b0 = bs[h * 8 + 2 * t];
            float b1 = bs[h * 8 + 2 * t + 1];
#pragma unroll
            for (int m = 0; m < 8; ++m) {
                acc[m][h][0] = b0; acc[m][h][1] = b1;
                acc[m][h][2] = b0; acc[m][h][3] = b1;
            }
        }
    }

#pragma unroll 1
    for (int ky = 0; ky < 5; ++ky) {
#pragma unroll 1
        for (int kx = 0; kx < 5; ++kx) {
            // A view for this tap: px -> patch[r+ky][px+kx]
            const char* arow = smem + SA
                + ((r + ky) * PW + kx) * 16 + g * 16 + t * 4;
            const char* brow = smem + SB + (ky * 5 + kx) * 256 + lane * 4;
            unsigned b0 = *reinterpret_cast<const unsigned*>(brow);
            unsigned b1 = *reinterpret_cast<const unsigned*>(brow + 128);
#pragma unroll
            for (int m = 0; m < 8; ++m) {
                unsigned a0 = *reinterpret_cast<const unsigned*>(arow + m * 256);
                unsigned a1 = *reinterpret_cast<const unsigned*>(arow + m * 256 + 128);
                asm volatile(
                    "mma.sync.aligned.m16n8k8.row.col.f32.f16.f16.f32 "
                    "{%0,%1,%2,%3}, {%4,%5}, {%6}, {%0,%1,%2,%3};"
                    : "+f"(acc[m][0][0]), "+f"(acc[m][0][1]),
                      "+f"(acc[m][0][2]), "+f"(acc[m][0][3])
                    : "r"(a0), "r"(a1), "r"(b0));
                asm volatile(
                    "mma.sync.aligned.m16n8k8.row.col.f32.f16.f16.f32 "
                    "{%0,%1,%2,%3}, {%4,%5}, {%6}, {%0,%1,%2,%3};"
                    : "+f"(acc[m][1][0]), "+f"(acc[m][1][1]),
                      "+f"(acc[m][1][2]), "+f"(acc[m][1][3])
                    : "r"(a0), "r"(a1), "r"(b1));
            }
        }
    }

    // ---- store: c0=(px g, oc 2t), c1=(g, 2t+1), c2=(g+8, 2t), c3=(g+8, 2t+1) ----
    const int oy = y0 + r;
    if (oy < OH) {
#pragma unroll 1
        for (int m = 0; m < 8; ++m) {
            int ox0 = x0 + m * 16 + g;       // max 503 < 508, always valid
            int ox1 = ox0 + 8;               // can reach 511 -> guard
#pragma unroll
            for (int h = 0; h < 2; ++h) {
                int oc0 = h * 8 + 2 * t;
                size_t base0 = (((size_t)b * 16 + oc0) * OH + oy) * OW;
                size_t base1 = base0 + (size_t)OH * OW;   // oc0 + 1
                out[base0 + ox0] = acc[m][h][0];
                out[base1 + ox0] = acc[m][h][1];
                if (ox1 < OW) {
                    out[base0 + ox1] = acc[m][h][2];
                    out[base1 + ox1] = acc[m][h][3];
                }
            }
        }
    }
}

extern "C" void kernel_launch(void* const* d_in, const int* in_sizes, int n_in,
                              void* d_out, int out_size)
{
    const float* x    = (const float*)d_in[0];  // [32,6,512,512]
    const float* wgt  = (const float*)d_in[1];  // [16,6,5,5]
    const float* bias = (const float*)d_in[2];  // [16]
    float* out = (float*)d_out;                 // [32,16,508,508]

    dim3 grid((OW + TW - 1) / TW,    // 4
              (OH + TH - 1) / TH,    // 64
              32);                   // batch
    c3_hmma<<<grid, 256>>>(x, wgt, bias, out);
}